// round 7
// baseline (speedup 1.0000x reference)
#include <cuda_runtime.h>
#include <cuda_bf16.h>
#include <cstdint>

// ---------------- problem constants ----------------
#define NSAMP  15552
#define NJ     17
#define MROWS  (NSAMP*NJ)        // 264384
#define MTILES 2066              // ceil(MROWS/128)
#define MPAD   (MTILES*128)      // 264448
#define DIN    256
#define DOUT   256
#define DMID   512
#define EPSV   1e-5f

// ---------------- scratch (device globals; no runtime alloc) ----------------
static __device__ __nv_bfloat16 g_xa_hi [(size_t)MPAD * DIN];
static __device__ __nv_bfloat16 g_xa_lo [(size_t)MPAD * DIN];
static __device__ float         g_h     [(size_t)MPAD * DOUT];
static __device__ __nv_bfloat16 g_hn_hi [(size_t)MPAD * DOUT];
static __device__ __nv_bfloat16 g_hn_lo [(size_t)MPAD * DOUT];
static __device__ __nv_bfloat16 g_mid_hi[(size_t)MPAD * DMID];
static __device__ __nv_bfloat16 g_mid_lo[(size_t)MPAD * DMID];

static __device__ __nv_bfloat16 g_w_hi  [DOUT * DIN];
static __device__ __nv_bfloat16 g_w_lo  [DOUT * DIN];
static __device__ __nv_bfloat16 g_mw1_hi[DMID * DOUT];
static __device__ __nv_bfloat16 g_mw1_lo[DMID * DOUT];
static __device__ __nv_bfloat16 g_mw2_hi[DOUT * DMID];
static __device__ __nv_bfloat16 g_mw2_lo[DOUT * DMID];

static __device__ float g_bias [DOUT];
static __device__ float g_rs   [NJ];
static __device__ float g_bnsum[DOUT];
static __device__ float g_bnsq [DOUT];
static __device__ float g_scale[DOUT];
static __device__ float g_shift[DOUT];

// ---------------- helpers ----------------
__device__ __forceinline__ uint32_t smem_u32(const void* p) {
    uint32_t a;
    asm("{ .reg .u64 t; cvta.to.shared.u64 t, %1; cvt.u32.u64 %0, t; }" : "=r"(a) : "l"(p));
    return a;
}
__device__ __forceinline__ void ldsm4(uint32_t* r, uint32_t addr) {
    asm volatile("ldmatrix.sync.aligned.m8n8.x4.shared.b16 {%0,%1,%2,%3}, [%4];"
                 : "=r"(r[0]), "=r"(r[1]), "=r"(r[2]), "=r"(r[3]) : "r"(addr));
}
__device__ __forceinline__ void mma16816(float* c, const uint32_t* a, uint32_t b0, uint32_t b1) {
    asm volatile("mma.sync.aligned.m16n8k16.row.col.f32.bf16.bf16.f32 "
                 "{%0,%1,%2,%3}, {%4,%5,%6,%7}, {%8,%9}, {%0,%1,%2,%3};"
                 : "+f"(c[0]), "+f"(c[1]), "+f"(c[2]), "+f"(c[3])
                 : "r"(a[0]), "r"(a[1]), "r"(a[2]), "r"(a[3]), "r"(b0), "r"(b1));
}
__device__ __forceinline__ void cpa16(uint32_t dst, const void* src) {
    asm volatile("cp.async.ca.shared.global [%0], [%1], 16;" :: "r"(dst), "l"(src));
}
#define CP_COMMIT() asm volatile("cp.async.commit_group;" ::: "memory")
#define CP_WAIT0()  asm volatile("cp.async.wait_group 0;" ::: "memory")

__device__ __forceinline__ void split_bf16(float v, __nv_bfloat16& hi, __nv_bfloat16& lo) {
    hi = __float2bfloat16(v);
    lo = __float2bfloat16(v - __bfloat162float(hi));
}
__device__ __forceinline__ uint32_t pack_bf16(__nv_bfloat16 a, __nv_bfloat16 b) {
    uint32_t r = ((uint32_t)*(unsigned short*)&b << 16) | (uint32_t)*(unsigned short*)&a;
    return r;
}

// ---------------- K0: prep ----------------
__global__ void prep_kernel(const float* __restrict__ w1, const float* __restrict__ b1,
                            const float* __restrict__ w2, const float* __restrict__ b2,
                            const float* __restrict__ adj,
                            const float* __restrict__ mw1, const float* __restrict__ mw2) {
    int bid = blockIdx.x, tid = threadIdx.x;
    if (bid < 256) {
        int i = bid * 256 + tid;
        split_bf16(w1[i] + w2[i], g_w_hi[i], g_w_lo[i]);
    } else if (bid < 768) {
        int i = (bid - 256) * 256 + tid;
        split_bf16(mw1[i], g_mw1_hi[i], g_mw1_lo[i]);
    } else {
        int i = (bid - 768) * 256 + tid;
        split_bf16(mw2[i], g_mw2_hi[i], g_mw2_lo[i]);
    }
    if (bid == 0) {
        g_bias[tid]  = b1[tid] + b2[tid];
        g_bnsum[tid] = 0.0f;
        g_bnsq[tid]  = 0.0f;
        if (tid < NJ) {
            float s = 0.0f;
            #pragma unroll
            for (int j = 0; j < NJ; j++) s += adj[tid * NJ + j];
            g_rs[tid] = s;
        }
    }
}

// zero the padded tail rows of xa / hn
__global__ void padzero_kernel() {
    int idx = blockIdx.x * 256 + threadIdx.x;       // [0, 65536)
    int region = idx >> 14, off = idx & 16383;
    size_t p = (size_t)MROWS * 256 + off;
    __nv_bfloat16 z = __float2bfloat16(0.0f);
    if      (region == 0) g_xa_hi[p] = z;
    else if (region == 1) g_xa_lo[p] = z;
    else if (region == 2) g_hn_hi[p] = z;
    else                  g_hn_lo[p] = z;
}

// ---------------- K1: adjacency aggregation -> split bf16 ----------------
__global__ void agg_kernel(const float* __restrict__ x, const float* __restrict__ adj) {
    __shared__ float sadj[NJ * NJ];
    int t = threadIdx.x;
    for (int i = t; i < NJ * NJ; i += 256) sadj[i] = adj[i];
    __syncthreads();
    size_t base = (size_t)blockIdx.x * NJ * DIN + t;
    const float* xs = x + base;
    float xv[NJ];
    #pragma unroll
    for (int j = 0; j < NJ; j++) xv[j] = xs[(size_t)j * DIN];
    #pragma unroll
    for (int i = 0; i < NJ; i++) {
        float a = 0.0f;
        #pragma unroll
        for (int j = 0; j < NJ; j++) a = fmaf(sadj[i * NJ + j], xv[j], a);
        __nv_bfloat16 hi, lo;
        split_bf16(a, hi, lo);
        g_xa_hi[base + (size_t)i * DIN] = hi;
        g_xa_lo[base + (size_t)i * DIN] = lo;
    }
}

// ---------------- HMMA split-bf16 GEMM, pipelined double buffer ----------------
// Block 128(M) x 128(N), BK=32 per stage, hi|lo packed per 128B row
// (chunks 0..3 = hi, 4..7 = lo). Stage = A 16K + B 16K = 32 KB; 2 stages = 64 KB.
// 8 warps (2M x 4N), warp tile 64x32. D = Ah*Bh + Ah*Bl + Al*Bh, fp32 accum.
// ONE __syncthreads per chunk; next stage issued before compute (overlapped).
template<int K, int ASEL, int OUTM>
__global__ void __launch_bounds__(256, 2)
mma_gemm(const float* __restrict__ biasx, float* __restrict__ Cout) {
    extern __shared__ char smem[];
    const uint32_t sb = smem_u32(smem);
    constexpr uint32_t STG = 32768;      // stage stride
    constexpr uint32_t BOF = 16384;      // B offset within stage

    int tid = threadIdx.x;
    int wid = tid >> 5, lane = tid & 31;
    int wm0 = (wid & 1) * 64;
    int wn0 = (wid >> 1) * 32;

    size_t m0 = (size_t)blockIdx.y * 128;
    int    n0 = blockIdx.x * 128;

    const __nv_bfloat16 *Ah, *Al, *Bh, *Bl;
    if      (ASEL == 0) { Ah = g_xa_hi;  Al = g_xa_lo;  Bh = g_w_hi;   Bl = g_w_lo;   }
    else if (ASEL == 1) { Ah = g_hn_hi;  Al = g_hn_lo;  Bh = g_mw1_hi; Bl = g_mw1_lo; }
    else                { Ah = g_mid_hi; Al = g_mid_lo; Bh = g_mw2_hi; Bl = g_mw2_lo; }

    float acc[4][4][4] = {};

    // ldmatrix lane addressing (relative offsets within a stage)
    int la = lane & 15, lb = lane >> 4;
    int swA = la & 7;
    uint32_t aRel = (uint32_t)(wm0 + la) * 128u;               // + mf*2048
    uint32_t browB = (uint32_t)(wn0 + (lane & 7) + ((lane >> 4) << 3));
    int bCk = (lane >> 3) & 1;
    int swB = lane & 7;
    uint32_t bRel = BOF + browB * 128u;                        // +2048 for 2nd frag

    // staging: per thread 4 rows x (A,B); hoisted pointers, bumped 64B per chunk
    int srr = tid >> 3, scc = tid & 7;                         // scc: 0-3 hi, 4-7 lo
    const char* pA[4];
    const char* pB[4];
    uint32_t soff[4];
    {
        const __nv_bfloat16* baseA = (scc < 4) ? Ah : Al;
        const __nv_bfloat16* baseB = (scc < 4) ? Bh : Bl;
        int cs = (scc & 3) * 8;
        #pragma unroll
        for (int q = 0; q < 4; q++) {
            int r = srr + q * 32;            // 0..127
            soff[q] = (uint32_t)(r * 128 + ((scc ^ (r & 7)) << 4));
            pA[q] = (const char*)(baseA + (m0 + r) * (size_t)K + cs);
            pB[q] = (const char*)(baseB + (size_t)(n0 + r) * K + cs);
        }
    }

    const int NCH = K / 32;

    // prologue: stage chunk 0 into buffer 0
    #pragma unroll
    for (int q = 0; q < 4; q++) {
        cpa16(sb + soff[q], pA[q]);
        cpa16(sb + BOF + soff[q], pB[q]);
        pA[q] += 64; pB[q] += 64;
    }
    CP_COMMIT();

    for (int kc = 0; kc < NCH; kc++) {
        CP_WAIT0();
        __syncthreads();

        // overlap: issue next stage before computing current
        if (kc + 1 < NCH) {
            uint32_t bufbase = sb + (uint32_t)((kc + 1) & 1) * STG;
            #pragma unroll
            for (int q = 0; q < 4; q++) {
                cpa16(bufbase + soff[q], pA[q]);
                cpa16(bufbase + BOF + soff[q], pB[q]);
                pA[q] += 64; pB[q] += 64;
            }
            CP_COMMIT();
        }

        uint32_t bb = sb + (uint32_t)(kc & 1) * STG;
        #pragma unroll
        for (int ks = 0; ks < 2; ks++) {
            int ca = ks * 2 + lb;            // hi chunks 0..3
            int cb = ks * 2 + bCk;
            uint32_t choAh = (uint32_t)((ca ^ swA) << 4);
            uint32_t choAl = (uint32_t)(((ca + 4) ^ swA) << 4);
            uint32_t choBh = (uint32_t)((cb ^ swB) << 4);
            uint32_t choBl = (uint32_t)(((cb + 4) ^ swB) << 4);
            uint32_t ah[4][4], al[4][4];
            uint32_t bh0[4], bl0[4], bh1[4], bl1[4];
            #pragma unroll
            for (int mf = 0; mf < 4; mf++) {
                ldsm4(ah[mf], bb + aRel + mf * 2048u + choAh);
                ldsm4(al[mf], bb + aRel + mf * 2048u + choAl);
            }
            ldsm4(bh0, bb + bRel + choBh);
            ldsm4(bl0, bb + bRel + choBl);
            ldsm4(bh1, bb + bRel + 2048u + choBh);
            ldsm4(bl1, bb + bRel + 2048u + choBl);
            #pragma unroll
            for (int mf = 0; mf < 4; mf++) {
                #pragma unroll
                for (int nf = 0; nf < 4; nf++) {
                    const uint32_t* BHf = (nf < 2) ? bh0 : bh1;
                    const uint32_t* BLf = (nf < 2) ? bl0 : bl1;
                    uint32_t bH0 = BHf[(nf & 1) * 2], bH1 = BHf[(nf & 1) * 2 + 1];
                    uint32_t bL0 = BLf[(nf & 1) * 2], bL1 = BLf[(nf & 1) * 2 + 1];
                    float* C = acc[mf][nf];
                    mma16816(C, ah[mf], bH0, bH1);
                    mma16816(C, ah[mf], bL0, bL1);
                    mma16816(C, al[mf], bH0, bH1);
                }
            }
        }
    }
    __syncthreads();

    // ---------------- epilogue ----------------
    int colq = 2 * (lane & 3);
    int rowq = lane >> 2;

    if (OUTM == 0) {
        // stats scratch aliases dead staging smem: 128 sums + 128 sqs
        float* sstat = (float*)smem;
        sstat[tid] = 0.0f;
        __syncthreads();

        float lsum[8], lsq[8];
        #pragma unroll
        for (int j = 0; j < 8; j++) { lsum[j] = 0.0f; lsq[j] = 0.0f; }
        #pragma unroll
        for (int mf = 0; mf < 4; mf++) {
            size_t r0 = m0 + wm0 + mf * 16 + rowq;
            size_t r1 = r0 + 8;
            float rs0 = g_rs[(int)(r0 % NJ)];
            float rs1 = g_rs[(int)(r1 % NJ)];
            bool v0 = r0 < MROWS, v1 = r1 < MROWS;
            #pragma unroll
            for (int nf = 0; nf < 4; nf++) {
                int c = n0 + wn0 + nf * 8 + colq;
                float b0 = g_bias[c], b1 = g_bias[c + 1];
                float x0 = fmaxf(acc[mf][nf][0] + rs0 * b0, 0.0f);
                float x1 = fmaxf(acc[mf][nf][1] + rs0 * b1, 0.0f);
                float x2 = fmaxf(acc[mf][nf][2] + rs1 * b0, 0.0f);
                float x3 = fmaxf(acc[mf][nf][3] + rs1 * b1, 0.0f);
                *(float2*)(g_h + r0 * DOUT + c) = make_float2(x0, x1);
                *(float2*)(g_h + r1 * DOUT + c) = make_float2(x2, x3);
                if (v0) {
                    lsum[nf*2]   += x0; lsq[nf*2]   = fmaf(x0, x0, lsq[nf*2]);
                    lsum[nf*2+1] += x1; lsq[nf*2+1] = fmaf(x1, x1, lsq[nf*2+1]);
                }
                if (v1) {
                    lsum[nf*2]   += x2; lsq[nf*2]   = fmaf(x2, x2, lsq[nf*2]);
                    lsum[nf*2+1] += x3; lsq[nf*2+1] = fmaf(x3, x3, lsq[nf*2+1]);
                }
            }
        }
        #pragma unroll
        for (int o = 4; o < 32; o <<= 1) {
            #pragma unroll
            for (int j = 0; j < 8; j++) {
                lsum[j] += __shfl_xor_sync(0xffffffffu, lsum[j], o);
                lsq[j]  += __shfl_xor_sync(0xffffffffu, lsq[j],  o);
            }
        }
        if (lane < 4) {
            #pragma unroll
            for (int nf = 0; nf < 4; nf++) {
                #pragma unroll
                for (int j = 0; j < 2; j++) {
                    int cb = wn0 + nf * 8 + 2 * lane + j;
                    atomicAdd(&sstat[cb],       lsum[nf*2 + j]);
                    atomicAdd(&sstat[128 + cb], lsq[nf*2 + j]);
                }
            }
        }
        __syncthreads();
        if (tid < 128) atomicAdd(&g_bnsum[n0 + tid], sstat[tid]);
        else           atomicAdd(&g_bnsq [n0 + tid - 128], sstat[tid]);
    } else if (OUTM == 1) {
        #pragma unroll
        for (int mf = 0; mf < 4; mf++) {
            size_t r0 = m0 + wm0 + mf * 16 + rowq;
            size_t r1 = r0 + 8;
            #pragma unroll
            for (int nf = 0; nf < 4; nf++) {
                int c = n0 + wn0 + nf * 8 + colq;
                float b0 = biasx[c], b1 = biasx[c + 1];
                float x0 = fmaxf(acc[mf][nf][0] + b0, 0.0f);
                float x1 = fmaxf(acc[mf][nf][1] + b1, 0.0f);
                float x2 = fmaxf(acc[mf][nf][2] + b0, 0.0f);
                float x3 = fmaxf(acc[mf][nf][3] + b1, 0.0f);
                __nv_bfloat16 h0, l0, h1, l1, h2, l2, h3, l3;
                split_bf16(x0, h0, l0); split_bf16(x1, h1, l1);
                split_bf16(x2, h2, l2); split_bf16(x3, h3, l3);
                *(uint32_t*)(g_mid_hi + r0 * DMID + c) = pack_bf16(h0, h1);
                *(uint32_t*)(g_mid_lo + r0 * DMID + c) = pack_bf16(l0, l1);
                *(uint32_t*)(g_mid_hi + r1 * DMID + c) = pack_bf16(h2, h3);
                *(uint32_t*)(g_mid_lo + r1 * DMID + c) = pack_bf16(l2, l3);
            }
        }
    } else {
        #pragma unroll
        for (int mf = 0; mf < 4; mf++) {
            size_t r0 = m0 + wm0 + mf * 16 + rowq;
            size_t r1 = r0 + 8;
            #pragma unroll
            for (int nf = 0; nf < 4; nf++) {
                int c = n0 + wn0 + nf * 8 + colq;
                float b0 = biasx[c], b1 = biasx[c + 1];
                if (r0 < MROWS)
                    *(float2*)(Cout + r0 * DOUT + c) =
                        make_float2(acc[mf][nf][0] + b0, acc[mf][nf][1] + b1);
                if (r1 < MROWS)
                    *(float2*)(Cout + r1 * DOUT + c) =
                        make_float2(acc[mf][nf][2] + b0, acc[mf][nf][3] + b1);
            }
        }
    }
}

// ---------------- BN finalize ----------------
__global__ void bnfin_kernel(const float* __restrict__ bng, const float* __restrict__ bnb) {
    int c = threadIdx.x;
    const float inv = 1.0f / (float)MROWS;
    float mean = g_bnsum[c] * inv;
    float var  = g_bnsq[c] * inv - mean * mean;
    float sc   = bng[c] * rsqrtf(var + EPSV);
    g_scale[c] = sc;
    g_shift[c] = bnb[c] - mean * sc;
}

// ---------------- fused BN + LayerNorm -> split bf16 hn ----------------
__global__ void bnln_kernel(const float* __restrict__ lng, const float* __restrict__ lnb) {
    int warp = threadIdx.x >> 5, lane = threadIdx.x & 31;
    size_t row = (size_t)blockIdx.x * 8 + warp;
    const float* hr = g_h + row * DOUT;
    float v[8];
    float s = 0.0f, sq = 0.0f;
    #pragma unroll
    for (int e = 0; e < 8; e++) {
        int c = lane + 32 * e;
        float t = fmaf(hr[c], g_scale[c], g_shift[c]);
        v[e] = t; s += t; sq = fmaf(t, t, sq);
    }
    #pragma unroll
    for (int o = 16; o > 0; o >>= 1) {
        s  += __shfl_xor_sync(0xffffffffu, s,  o);
        sq += __shfl_xor_sync(0xffffffffu, sq, o);
    }
    float mu  = s * (1.0f / DOUT);
    float var = sq * (1.0f / DOUT) - mu * mu;
    float inv = rsqrtf(var + EPSV);
    #pragma unroll
    for (int e = 0; e < 8; e++) {
        int c = lane + 32 * e;
        float o = fmaf((v[e] - mu) * inv, lng[c], lnb[c]);
        __nv_bfloat16 hi, lo;
        split_bf16(o, hi, lo);
        g_hn_hi[row * DOUT + c] = hi;
        g_hn_lo[row * DOUT + c] = lo;
    }
}

// ---------------------------------------------------------------------------
extern "C" void kernel_launch(void* const* d_in, const int* in_sizes, int n_in,
                              void* d_out, int out_size) {
    const float* x   = (const float*)d_in[0];
    const float* adj = (const float*)d_in[1];
    const float* w1  = (const float*)d_in[2];
    const float* b1  = (const float*)d_in[3];
    const float* w2  = (const float*)d_in[4];
    const float* b2  = (const float*)d_in[5];
    const float* bng = (const float*)d_in[6];
    const float* bnb = (const float*)d_in[7];
    const float* lng = (const float*)d_in[8];
    const float* lnb = (const float*)d_in[9];
    const float* mw1 = (const float*)d_in[10];
    const float* mb1 = (const float*)d_in[11];
    const float* mw2 = (const float*)d_in[12];
    const float* mb2 = (const float*)d_in[13];
    float* out = (float*)d_out;

    const int SMEM_SZ = 65536;   // 64 KB dynamic (2 x 32 KB stages), zero static

    // host-side config, not an allocation; idempotent, capture-safe
    cudaFuncSetAttribute(mma_gemm<256, 0, 0>, cudaFuncAttributeMaxDynamicSharedMemorySize, SMEM_SZ);
    cudaFuncSetAttribute(mma_gemm<256, 1, 1>, cudaFuncAttributeMaxDynamicSharedMemorySize, SMEM_SZ);
    cudaFuncSetAttribute(mma_gemm<512, 2, 2>, cudaFuncAttributeMaxDynamicSharedMemorySize, SMEM_SZ);

    prep_kernel<<<1280, 256>>>(w1, b1, w2, b2, adj, mw1, mw2);
    padzero_kernel<<<256, 256>>>();
    agg_kernel<<<NSAMP, 256>>>(x, adj);
    // GEMM1: h = relu(xa @ (w1+w2)^T + rs*bias), fused BN stats
    mma_gemm<256, 0, 0><<<dim3(2, MTILES), 256, SMEM_SZ>>>(nullptr, nullptr);
    bnfin_kernel<<<1, DOUT>>>(bng, bnb);
    bnln_kernel<<<MROWS / 8, 256>>>(lng, lnb);
    // GEMM2: mid = relu(hn @ mlp_w1^T + mlp_b1)
    mma_gemm<256, 1, 1><<<dim3(4, MTILES), 256, SMEM_SZ>>>(mb1, nullptr);
    // GEMM3: out = mid @ mlp_w2^T + mlp_b2
    mma_gemm<512, 2, 2><<<dim3(2, MTILES), 256, SMEM_SZ>>>(mb2, out);
}

// round 8
// speedup vs baseline: 1.1627x; 1.1627x over previous
#include <cuda_runtime.h>
#include <cuda_bf16.h>
#include <cstdint>

// ---------------- problem constants ----------------
#define NSAMP  15552
#define NJ     17
#define MROWS  (NSAMP*NJ)        // 264384
#define MTILES 2066              // ceil(MROWS/128)
#define MPAD   (MTILES*128)      // 264448
#define DIN    256
#define DOUT   256
#define DMID   512
#define EPSV   1e-5f

// ---------------- scratch (device globals; no runtime alloc) ----------------
static __device__ __nv_bfloat16 g_xa_hi [(size_t)MPAD * DIN];
static __device__ __nv_bfloat16 g_xa_lo [(size_t)MPAD * DIN];
static __device__ float         g_h     [(size_t)MPAD * DOUT];
static __device__ __nv_bfloat16 g_hn_hi [(size_t)MPAD * DOUT];
static __device__ __nv_bfloat16 g_hn_lo [(size_t)MPAD * DOUT];
static __device__ __nv_bfloat16 g_mid_hi[(size_t)MPAD * DMID];
static __device__ __nv_bfloat16 g_mid_lo[(size_t)MPAD * DMID];

static __device__ __nv_bfloat16 g_w_hi  [DOUT * DIN];
static __device__ __nv_bfloat16 g_w_lo  [DOUT * DIN];
static __device__ __nv_bfloat16 g_mw1_hi[DMID * DOUT];
static __device__ __nv_bfloat16 g_mw1_lo[DMID * DOUT];
static __device__ __nv_bfloat16 g_mw2_hi[DOUT * DMID];
static __device__ __nv_bfloat16 g_mw2_lo[DOUT * DMID];

static __device__ float g_bias [DOUT];
static __device__ float g_rs   [NJ];
static __device__ float g_bnsum[DOUT];
static __device__ float g_bnsq [DOUT];
static __device__ float g_scale[DOUT];
static __device__ float g_shift[DOUT];

// ---------------- helpers ----------------
__device__ __forceinline__ uint32_t smem_u32(const void* p) {
    uint32_t a;
    asm("{ .reg .u64 t; cvta.to.shared.u64 t, %1; cvt.u32.u64 %0, t; }" : "=r"(a) : "l"(p));
    return a;
}
__device__ __forceinline__ void ldsm4(uint32_t* r, uint32_t addr) {
    asm volatile("ldmatrix.sync.aligned.m8n8.x4.shared.b16 {%0,%1,%2,%3}, [%4];"
                 : "=r"(r[0]), "=r"(r[1]), "=r"(r[2]), "=r"(r[3]) : "r"(addr));
}
__device__ __forceinline__ void mma16816(float* c, const uint32_t* a, uint32_t b0, uint32_t b1) {
    asm volatile("mma.sync.aligned.m16n8k16.row.col.f32.bf16.bf16.f32 "
                 "{%0,%1,%2,%3}, {%4,%5,%6,%7}, {%8,%9}, {%0,%1,%2,%3};"
                 : "+f"(c[0]), "+f"(c[1]), "+f"(c[2]), "+f"(c[3])
                 : "r"(a[0]), "r"(a[1]), "r"(a[2]), "r"(a[3]), "r"(b0), "r"(b1));
}
// L1-bypass async copy (L2 -> smem), 16B
__device__ __forceinline__ void cpa16(uint32_t dst, const void* src) {
    asm volatile("cp.async.cg.shared.global [%0], [%1], 16;" :: "r"(dst), "l"(src));
}
#define CP_COMMIT() asm volatile("cp.async.commit_group;" ::: "memory")
#define CP_WAIT0()  asm volatile("cp.async.wait_group 0;" ::: "memory")

__device__ __forceinline__ void split_bf16(float v, __nv_bfloat16& hi, __nv_bfloat16& lo) {
    hi = __float2bfloat16(v);
    lo = __float2bfloat16(v - __bfloat162float(hi));
}
__device__ __forceinline__ uint32_t pack_bf16(__nv_bfloat16 a, __nv_bfloat16 b) {
    uint32_t r = ((uint32_t)*(unsigned short*)&b << 16) | (uint32_t)*(unsigned short*)&a;
    return r;
}

// ---------------- K0: prep ----------------
__global__ void prep_kernel(const float* __restrict__ w1, const float* __restrict__ b1,
                            const float* __restrict__ w2, const float* __restrict__ b2,
                            const float* __restrict__ adj,
                            const float* __restrict__ mw1, const float* __restrict__ mw2) {
    int bid = blockIdx.x, tid = threadIdx.x;
    if (bid < 256) {
        int i = bid * 256 + tid;
        split_bf16(w1[i] + w2[i], g_w_hi[i], g_w_lo[i]);
    } else if (bid < 768) {
        int i = (bid - 256) * 256 + tid;
        split_bf16(mw1[i], g_mw1_hi[i], g_mw1_lo[i]);
    } else {
        int i = (bid - 768) * 256 + tid;
        split_bf16(mw2[i], g_mw2_hi[i], g_mw2_lo[i]);
    }
    if (bid == 0) {
        g_bias[tid]  = b1[tid] + b2[tid];
        g_bnsum[tid] = 0.0f;
        g_bnsq[tid]  = 0.0f;
        if (tid < NJ) {
            float s = 0.0f;
            #pragma unroll
            for (int j = 0; j < NJ; j++) s += adj[tid * NJ + j];
            g_rs[tid] = s;
        }
    }
}

// zero the padded tail rows of xa / hn
__global__ void padzero_kernel() {
    int idx = blockIdx.x * 256 + threadIdx.x;       // [0, 65536)
    int region = idx >> 14, off = idx & 16383;
    size_t p = (size_t)MROWS * 256 + off;
    __nv_bfloat16 z = __float2bfloat16(0.0f);
    if      (region == 0) g_xa_hi[p] = z;
    else if (region == 1) g_xa_lo[p] = z;
    else if (region == 2) g_hn_hi[p] = z;
    else                  g_hn_lo[p] = z;
}

// ---------------- K1: adjacency aggregation -> split bf16 ----------------
__global__ void agg_kernel(const float* __restrict__ x, const float* __restrict__ adj) {
    __shared__ float sadj[NJ * NJ];
    int t = threadIdx.x;
    for (int i = t; i < NJ * NJ; i += 256) sadj[i] = adj[i];
    __syncthreads();
    size_t base = (size_t)blockIdx.x * NJ * DIN + t;
    const float* xs = x + base;
    float xv[NJ];
    #pragma unroll
    for (int j = 0; j < NJ; j++) xv[j] = xs[(size_t)j * DIN];
    #pragma unroll
    for (int i = 0; i < NJ; i++) {
        float a = 0.0f;
        #pragma unroll
        for (int j = 0; j < NJ; j++) a = fmaf(sadj[i * NJ + j], xv[j], a);
        __nv_bfloat16 hi, lo;
        split_bf16(a, hi, lo);
        g_xa_hi[base + (size_t)i * DIN] = hi;
        g_xa_lo[base + (size_t)i * DIN] = lo;
    }
}

// ---------------- HMMA split-bf16 GEMM (round-5 structure) ----------------
// Block 128(M) x 128(N), BK=64, 8 warps (2M x 4N), warp tile 64x32.
// cp.async.cg staging (L1 bypass), 64 KB dynamic smem, no static smem.
// D = Ah*Bh + Ah*Bl + Al*Bh with fp32 accum.
template<int K, int ASEL, int OUTM>
__global__ void __launch_bounds__(256, 2)
mma_gemm(const float* __restrict__ biasx, float* __restrict__ Cout) {
    extern __shared__ char smem[];
    const uint32_t sb = smem_u32(smem);
    constexpr uint32_t AHI = 0, ALO = 16384, BHI = 32768, BLO = 49152;

    int tid = threadIdx.x;
    int wid = tid >> 5, lane = tid & 31;
    int wm0 = (wid & 1) * 64;
    int wn0 = (wid >> 1) * 32;

    size_t m0 = (size_t)blockIdx.y * 128;
    int    n0 = blockIdx.x * 128;

    const __nv_bfloat16 *Ah, *Al, *Bh, *Bl;
    if      (ASEL == 0) { Ah = g_xa_hi;  Al = g_xa_lo;  Bh = g_w_hi;   Bl = g_w_lo;   }
    else if (ASEL == 1) { Ah = g_hn_hi;  Al = g_hn_lo;  Bh = g_mw1_hi; Bl = g_mw1_lo; }
    else                { Ah = g_mid_hi; Al = g_mid_lo; Bh = g_mw2_hi; Bl = g_mw2_lo; }

    float acc[4][4][4] = {};

    // ldmatrix lane addressing
    int la = lane & 15, lb = lane >> 4;
    int swA = la & 7;                                  // row&7 for all A frags
    uint32_t aBase = sb + (uint32_t)(wm0 + la) * 128u; // +AHI/+ALO, +2048*mf
    uint32_t browB = (uint32_t)(wn0 + (lane & 7) + ((lane >> 4) << 3));
    int bCk = (lane >> 3) & 1;
    int swB = lane & 7;                                // row&7 for both B frags
    uint32_t bBase = sb + browB * 128u;                // +BHI/+BLO, +2048 for second

    // staging indices (per thread: 4 iterations x 4 regions x 16B)
    int srr = tid >> 3, scc = tid & 7;

    const int NCH = K / 64;
    #pragma unroll
    for (int kc = 0; kc < NCH; kc++) {
        #pragma unroll
        for (int q = 0; q < 4; q++) {
            int r = srr + q * 32;            // 0..127
            int c = scc;
            size_t goA = (m0 + r) * (size_t)K + kc * 64 + c * 8;
            size_t goB = (size_t)(n0 + r) * K + kc * 64 + c * 8;
            uint32_t so = (uint32_t)(r * 128 + ((c ^ (r & 7)) << 4));
            cpa16(sb + AHI + so, Ah + goA);
            cpa16(sb + ALO + so, Al + goA);
            cpa16(sb + BHI + so, Bh + goB);
            cpa16(sb + BLO + so, Bl + goB);
        }
        CP_COMMIT();
        CP_WAIT0();
        __syncthreads();

        #pragma unroll
        for (int ks = 0; ks < 4; ks++) {
            int ca = ks * 2 + lb;
            int cb = ks * 2 + bCk;
            uint32_t choA = (uint32_t)((ca ^ swA) << 4);
            uint32_t choB = (uint32_t)((cb ^ swB) << 4);
            uint32_t ah[4][4], al[4][4];
            uint32_t bh0[4], bl0[4], bh1[4], bl1[4];
            #pragma unroll
            for (int mf = 0; mf < 4; mf++) {
                ldsm4(ah[mf], aBase + AHI + mf * 2048u + choA);
                ldsm4(al[mf], aBase + ALO + mf * 2048u + choA);
            }
            ldsm4(bh0, bBase + BHI + choB);
            ldsm4(bl0, bBase + BLO + choB);
            ldsm4(bh1, bBase + BHI + 2048u + choB);
            ldsm4(bl1, bBase + BLO + 2048u + choB);
            #pragma unroll
            for (int mf = 0; mf < 4; mf++) {
                #pragma unroll
                for (int nf = 0; nf < 4; nf++) {
                    const uint32_t* BHf = (nf < 2) ? bh0 : bh1;
                    const uint32_t* BLf = (nf < 2) ? bl0 : bl1;
                    uint32_t bH0 = BHf[(nf & 1) * 2], bH1 = BHf[(nf & 1) * 2 + 1];
                    uint32_t bL0 = BLf[(nf & 1) * 2], bL1 = BLf[(nf & 1) * 2 + 1];
                    float* C = acc[mf][nf];
                    mma16816(C, ah[mf], bH0, bH1);
                    mma16816(C, ah[mf], bL0, bL1);
                    mma16816(C, al[mf], bH0, bH1);
                }
            }
        }
        __syncthreads();
    }

    // ---------------- epilogue ----------------
    int colq = 2 * (lane & 3);
    int rowq = lane >> 2;

    if (OUTM == 0) {
        // stats scratch aliases dead staging smem: 128 sums + 128 sqs
        float* sstat = (float*)smem;
        sstat[tid] = 0.0f;
        __syncthreads();

        float lsum[8], lsq[8];
        #pragma unroll
        for (int j = 0; j < 8; j++) { lsum[j] = 0.0f; lsq[j] = 0.0f; }
        #pragma unroll
        for (int mf = 0; mf < 4; mf++) {
            size_t r0 = m0 + wm0 + mf * 16 + rowq;
            size_t r1 = r0 + 8;
            float rs0 = g_rs[(int)(r0 % NJ)];
            float rs1 = g_rs[(int)(r1 % NJ)];
            bool v0 = r0 < MROWS, v1 = r1 < MROWS;
            #pragma unroll
            for (int nf = 0; nf < 4; nf++) {
                int c = n0 + wn0 + nf * 8 + colq;
                float b0 = g_bias[c], b1 = g_bias[c + 1];
                float x0 = fmaxf(acc[mf][nf][0] + rs0 * b0, 0.0f);
                float x1 = fmaxf(acc[mf][nf][1] + rs0 * b1, 0.0f);
                float x2 = fmaxf(acc[mf][nf][2] + rs1 * b0, 0.0f);
                float x3 = fmaxf(acc[mf][nf][3] + rs1 * b1, 0.0f);
                *(float2*)(g_h + r0 * DOUT + c) = make_float2(x0, x1);
                *(float2*)(g_h + r1 * DOUT + c) = make_float2(x2, x3);
                if (v0) {
                    lsum[nf*2]   += x0; lsq[nf*2]   = fmaf(x0, x0, lsq[nf*2]);
                    lsum[nf*2+1] += x1; lsq[nf*2+1] = fmaf(x1, x1, lsq[nf*2+1]);
                }
                if (v1) {
                    lsum[nf*2]   += x2; lsq[nf*2]   = fmaf(x2, x2, lsq[nf*2]);
                    lsum[nf*2+1] += x3; lsq[nf*2+1] = fmaf(x3, x3, lsq[nf*2+1]);
                }
            }
        }
        #pragma unroll
        for (int o = 4; o < 32; o <<= 1) {
            #pragma unroll
            for (int j = 0; j < 8; j++) {
                lsum[j] += __shfl_xor_sync(0xffffffffu, lsum[j], o);
                lsq[j]  += __shfl_xor_sync(0xffffffffu, lsq[j],  o);
            }
        }
        if (lane < 4) {
            #pragma unroll
            for (int nf = 0; nf < 4; nf++) {
                #pragma unroll
                for (int j = 0; j < 2; j++) {
                    int cb = wn0 + nf * 8 + 2 * lane + j;
                    atomicAdd(&sstat[cb],       lsum[nf*2 + j]);
                    atomicAdd(&sstat[128 + cb], lsq[nf*2 + j]);
                }
            }
        }
        __syncthreads();
        if (tid < 128) atomicAdd(&g_bnsum[n0 + tid], sstat[tid]);
        else           atomicAdd(&g_bnsq [n0 + tid - 128], sstat[tid]);
    } else if (OUTM == 1) {
        #pragma unroll
        for (int mf = 0; mf < 4; mf++) {
            size_t r0 = m0 + wm0 + mf * 16 + rowq;
            size_t r1 = r0 + 8;
            #pragma unroll
            for (int nf = 0; nf < 4; nf++) {
                int c = n0 + wn0 + nf * 8 + colq;
                float b0 = biasx[c], b1 = biasx[c + 1];
                float x0 = fmaxf(acc[mf][nf][0] + b0, 0.0f);
                float x1 = fmaxf(acc[mf][nf][1] + b1, 0.0f);
                float x2 = fmaxf(acc[mf][nf][2] + b0, 0.0f);
                float x3 = fmaxf(acc[mf][nf][3] + b1, 0.0f);
                __nv_bfloat16 h0, l0, h1, l1, h2, l2, h3, l3;
                split_bf16(x0, h0, l0); split_bf16(x1, h1, l1);
                split_bf16(x2, h2, l2); split_bf16(x3, h3, l3);
                *(uint32_t*)(g_mid_hi + r0 * DMID + c) = pack_bf16(h0, h1);
                *(uint32_t*)(g_mid_lo + r0 * DMID + c) = pack_bf16(l0, l1);
                *(uint32_t*)(g_mid_hi + r1 * DMID + c) = pack_bf16(h2, h3);
                *(uint32_t*)(g_mid_lo + r1 * DMID + c) = pack_bf16(l2, l3);
            }
        }
    } else {
        #pragma unroll
        for (int mf = 0; mf < 4; mf++) {
            size_t r0 = m0 + wm0 + mf * 16 + rowq;
            size_t r1 = r0 + 8;
            #pragma unroll
            for (int nf = 0; nf < 4; nf++) {
                int c = n0 + wn0 + nf * 8 + colq;
                float b0 = biasx[c], b1 = biasx[c + 1];
                if (r0 < MROWS)
                    *(float2*)(Cout + r0 * DOUT + c) =
                        make_float2(acc[mf][nf][0] + b0, acc[mf][nf][1] + b1);
                if (r1 < MROWS)
                    *(float2*)(Cout + r1 * DOUT + c) =
                        make_float2(acc[mf][nf][2] + b0, acc[mf][nf][3] + b1);
            }
        }
    }
}

// ---------------- BN finalize ----------------
__global__ void bnfin_kernel(const float* __restrict__ bng, const float* __restrict__ bnb) {
    int c = threadIdx.x;
    const float inv = 1.0f / (float)MROWS;
    float mean = g_bnsum[c] * inv;
    float var  = g_bnsq[c] * inv - mean * mean;
    float sc   = bng[c] * rsqrtf(var + EPSV);
    g_scale[c] = sc;
    g_shift[c] = bnb[c] - mean * sc;
}

// ---------------- fused BN + LayerNorm -> split bf16 hn ----------------
__global__ void bnln_kernel(const float* __restrict__ lng, const float* __restrict__ lnb) {
    int warp = threadIdx.x >> 5, lane = threadIdx.x & 31;
    size_t row = (size_t)blockIdx.x * 8 + warp;
    const float* hr = g_h + row * DOUT;
    float v[8];
    float s = 0.0f, sq = 0.0f;
    #pragma unroll
    for (int e = 0; e < 8; e++) {
        int c = lane + 32 * e;
        float t = fmaf(hr[c], g_scale[c], g_shift[c]);
        v[e] = t; s += t; sq = fmaf(t, t, sq);
    }
    #pragma unroll
    for (int o = 16; o > 0; o >>= 1) {
        s  += __shfl_xor_sync(0xffffffffu, s,  o);
        sq += __shfl_xor_sync(0xffffffffu, sq, o);
    }
    float mu  = s * (1.0f / DOUT);
    float var = sq * (1.0f / DOUT) - mu * mu;
    float inv = rsqrtf(var + EPSV);
    #pragma unroll
    for (int e = 0; e < 8; e++) {
        int c = lane + 32 * e;
        float o = fmaf((v[e] - mu) * inv, lng[c], lnb[c]);
        __nv_bfloat16 hi, lo;
        split_bf16(o, hi, lo);
        g_hn_hi[row * DOUT + c] = hi;
        g_hn_lo[row * DOUT + c] = lo;
    }
}

// ---------------------------------------------------------------------------
extern "C" void kernel_launch(void* const* d_in, const int* in_sizes, int n_in,
                              void* d_out, int out_size) {
    const float* x   = (const float*)d_in[0];
    const float* adj = (const float*)d_in[1];
    const float* w1  = (const float*)d_in[2];
    const float* b1  = (const float*)d_in[3];
    const float* w2  = (const float*)d_in[4];
    const float* b2  = (const float*)d_in[5];
    const float* bng = (const float*)d_in[6];
    const float* bnb = (const float*)d_in[7];
    const float* lng = (const float*)d_in[8];
    const float* lnb = (const float*)d_in[9];
    const float* mw1 = (const float*)d_in[10];
    const float* mb1 = (const float*)d_in[11];
    const float* mw2 = (const float*)d_in[12];
    const float* mb2 = (const float*)d_in[13];
    float* out = (float*)d_out;

    const int SMEM_SZ = 65536;   // 64 KB dynamic, zero static

    // host-side config, not an allocation; idempotent, capture-safe
    cudaFuncSetAttribute(mma_gemm<256, 0, 0>, cudaFuncAttributeMaxDynamicSharedMemorySize, SMEM_SZ);
    cudaFuncSetAttribute(mma_gemm<256, 1, 1>, cudaFuncAttributeMaxDynamicSharedMemorySize, SMEM_SZ);
    cudaFuncSetAttribute(mma_gemm<512, 2, 2>, cudaFuncAttributeMaxDynamicSharedMemorySize, SMEM_SZ);

    prep_kernel<<<1280, 256>>>(w1, b1, w2, b2, adj, mw1, mw2);
    padzero_kernel<<<256, 256>>>();
    agg_kernel<<<NSAMP, 256>>>(x, adj);
    // GEMM1: h = relu(xa @ (w1+w2)^T + rs*bias), fused BN stats
    mma_gemm<256, 0, 0><<<dim3(2, MTILES), 256, SMEM_SZ>>>(nullptr, nullptr);
    bnfin_kernel<<<1, DOUT>>>(bng, bnb);
    bnln_kernel<<<MROWS / 8, 256>>>(lng, lnb);
    // GEMM2: mid = relu(hn @ mlp_w1^T + mlp_b1)
    mma_gemm<256, 1, 1><<<dim3(4, MTILES), 256, SMEM_SZ>>>(mb1, nullptr);
    // GEMM3: out = mid @ mlp_w2^T + mlp_b2
    mma_gemm<512, 2, 2><<<dim3(2, MTILES), 256, SMEM_SZ>>>(mb2, out);
}

// round 9
// speedup vs baseline: 1.9017x; 1.6356x over previous
#include <cuda_runtime.h>
#include <cuda_bf16.h>
#include <cuda_fp16.h>
#include <cstdint>

// ---------------- problem constants ----------------
#define NSAMP  15552
#define NJ     17
#define MROWS  (NSAMP*NJ)        // 264384
#define MTILES 2066              // ceil(MROWS/128)
#define MPAD   (MTILES*128)      // 264448
#define DIN    256
#define DOUT   256
#define DMID   512
#define EPSV   1e-5f

// ---------------- scratch (device globals; no runtime alloc) ----------------
static __device__ __nv_bfloat16 g_xa_hi [(size_t)MPAD * DIN];
static __device__ __nv_bfloat16 g_xa_lo [(size_t)MPAD * DIN];
static __device__ float         g_h     [(size_t)MPAD * DOUT];
static __device__ __half        g_hnh   [(size_t)MPAD * DOUT];
static __device__ __half        g_midh  [(size_t)MPAD * DMID];

static __device__ __nv_bfloat16 g_w_hi  [DOUT * DIN];
static __device__ __nv_bfloat16 g_w_lo  [DOUT * DIN];
static __device__ __half        g_mw1h  [DMID * DOUT];
static __device__ __half        g_mw2h  [DOUT * DMID];

static __device__ float g_bias [DOUT];
static __device__ float g_rs   [NJ];
static __device__ float g_bnsum[DOUT];
static __device__ float g_bnsq [DOUT];
static __device__ float g_scale[DOUT];
static __device__ float g_shift[DOUT];

// ---------------- helpers ----------------
__device__ __forceinline__ uint32_t smem_u32(const void* p) {
    uint32_t a;
    asm("{ .reg .u64 t; cvta.to.shared.u64 t, %1; cvt.u32.u64 %0, t; }" : "=r"(a) : "l"(p));
    return a;
}
__device__ __forceinline__ void ldsm4(uint32_t* r, uint32_t addr) {
    asm volatile("ldmatrix.sync.aligned.m8n8.x4.shared.b16 {%0,%1,%2,%3}, [%4];"
                 : "=r"(r[0]), "=r"(r[1]), "=r"(r[2]), "=r"(r[3]) : "r"(addr));
}
__device__ __forceinline__ void mma_bf(float* c, const uint32_t* a, uint32_t b0, uint32_t b1) {
    asm volatile("mma.sync.aligned.m16n8k16.row.col.f32.bf16.bf16.f32 "
                 "{%0,%1,%2,%3}, {%4,%5,%6,%7}, {%8,%9}, {%0,%1,%2,%3};"
                 : "+f"(c[0]), "+f"(c[1]), "+f"(c[2]), "+f"(c[3])
                 : "r"(a[0]), "r"(a[1]), "r"(a[2]), "r"(a[3]), "r"(b0), "r"(b1));
}
__device__ __forceinline__ void mma_fp(float* c, const uint32_t* a, uint32_t b0, uint32_t b1) {
    asm volatile("mma.sync.aligned.m16n8k16.row.col.f32.f16.f16.f32 "
                 "{%0,%1,%2,%3}, {%4,%5,%6,%7}, {%8,%9}, {%0,%1,%2,%3};"
                 : "+f"(c[0]), "+f"(c[1]), "+f"(c[2]), "+f"(c[3])
                 : "r"(a[0]), "r"(a[1]), "r"(a[2]), "r"(a[3]), "r"(b0), "r"(b1));
}
// L1-bypass async copy (L2 -> smem), 16B
__device__ __forceinline__ void cpa16(uint32_t dst, const void* src) {
    asm volatile("cp.async.cg.shared.global [%0], [%1], 16;" :: "r"(dst), "l"(src));
}
#define CP_COMMIT() asm volatile("cp.async.commit_group;" ::: "memory")
#define CP_WAIT0()  asm volatile("cp.async.wait_group 0;" ::: "memory")

__device__ __forceinline__ void split_bf16(float v, __nv_bfloat16& hi, __nv_bfloat16& lo) {
    hi = __float2bfloat16(v);
    lo = __float2bfloat16(v - __bfloat162float(hi));
}
__device__ __forceinline__ uint32_t pack_half2(float a, float b) {
    __half2 h = __floats2half2_rn(a, b);
    return *(uint32_t*)&h;
}

// ---------------- K0: prep ----------------
__global__ void prep_kernel(const float* __restrict__ w1, const float* __restrict__ b1,
                            const float* __restrict__ w2, const float* __restrict__ b2,
                            const float* __restrict__ adj,
                            const float* __restrict__ mw1, const float* __restrict__ mw2) {
    int bid = blockIdx.x, tid = threadIdx.x;
    if (bid < 256) {
        int i = bid * 256 + tid;
        split_bf16(w1[i] + w2[i], g_w_hi[i], g_w_lo[i]);
    } else if (bid < 768) {
        int i = (bid - 256) * 256 + tid;
        g_mw1h[i] = __float2half_rn(mw1[i]);
    } else {
        int i = (bid - 768) * 256 + tid;
        g_mw2h[i] = __float2half_rn(mw2[i]);
    }
    if (bid == 0) {
        g_bias[tid]  = b1[tid] + b2[tid];
        g_bnsum[tid] = 0.0f;
        g_bnsq[tid]  = 0.0f;
        if (tid < NJ) {
            float s = 0.0f;
            #pragma unroll
            for (int j = 0; j < NJ; j++) s += adj[tid * NJ + j];
            g_rs[tid] = s;
        }
    }
}

// zero the padded tail rows of xa (bf16) and hn (half)
__global__ void padzero_kernel() {
    int idx = blockIdx.x * 256 + threadIdx.x;       // [0, 49152)
    int region = idx >> 14, off = idx & 16383;
    size_t p = (size_t)MROWS * 256 + off;
    if      (region == 0) g_xa_hi[p] = __float2bfloat16(0.0f);
    else if (region == 1) g_xa_lo[p] = __float2bfloat16(0.0f);
    else                  g_hnh[p]   = __float2half(0.0f);
}

// ---------------- K1: adjacency aggregation -> split bf16 ----------------
__global__ void agg_kernel(const float* __restrict__ x, const float* __restrict__ adj) {
    __shared__ float sadj[NJ * NJ];
    int t = threadIdx.x;
    for (int i = t; i < NJ * NJ; i += 256) sadj[i] = adj[i];
    __syncthreads();
    size_t base = (size_t)blockIdx.x * NJ * DIN + t;
    const float* xs = x + base;
    float xv[NJ];
    #pragma unroll
    for (int j = 0; j < NJ; j++) xv[j] = xs[(size_t)j * DIN];
    #pragma unroll
    for (int i = 0; i < NJ; i++) {
        float a = 0.0f;
        #pragma unroll
        for (int j = 0; j < NJ; j++) a = fmaf(sadj[i * NJ + j], xv[j], a);
        __nv_bfloat16 hi, lo;
        split_bf16(a, hi, lo);
        g_xa_hi[base + (size_t)i * DIN] = hi;
        g_xa_lo[base + (size_t)i * DIN] = lo;
    }
}

// ---------------- GEMM1: HMMA split-bf16 (round-8 structure, unchanged) ----------------
// Block 128x128, BK=64, 8 warps (2M x 4N), warp tile 64x32.
// h = relu(xa @ (w1+w2)^T + rs*bias), fused BN stats.
__global__ void __launch_bounds__(256, 2)
mma_gemm1() {
    extern __shared__ char smem[];
    const uint32_t sb = smem_u32(smem);
    constexpr uint32_t AHI = 0, ALO = 16384, BHI = 32768, BLO = 49152;
    constexpr int K = DIN;

    int tid = threadIdx.x;
    int wid = tid >> 5, lane = tid & 31;
    int wm0 = (wid & 1) * 64;
    int wn0 = (wid >> 1) * 32;

    size_t m0 = (size_t)blockIdx.y * 128;
    int    n0 = blockIdx.x * 128;

    float acc[4][4][4] = {};

    int la = lane & 15, lb = lane >> 4;
    int swA = la & 7;
    uint32_t aBase = sb + (uint32_t)(wm0 + la) * 128u;
    uint32_t browB = (uint32_t)(wn0 + (lane & 7) + ((lane >> 4) << 3));
    int bCk = (lane >> 3) & 1;
    int swB = lane & 7;
    uint32_t bBase = sb + browB * 128u;

    int srr = tid >> 3, scc = tid & 7;

    #pragma unroll
    for (int kc = 0; kc < K / 64; kc++) {
        #pragma unroll
        for (int q = 0; q < 4; q++) {
            int r = srr + q * 32;
            size_t goA = (m0 + r) * (size_t)K + kc * 64 + scc * 8;
            size_t goB = (size_t)(n0 + r) * K + kc * 64 + scc * 8;
            uint32_t so = (uint32_t)(r * 128 + ((scc ^ (r & 7)) << 4));
            cpa16(sb + AHI + so, g_xa_hi + goA);
            cpa16(sb + ALO + so, g_xa_lo + goA);
            cpa16(sb + BHI + so, g_w_hi + goB);
            cpa16(sb + BLO + so, g_w_lo + goB);
        }
        CP_COMMIT();
        CP_WAIT0();
        __syncthreads();

        #pragma unroll
        for (int ks = 0; ks < 4; ks++) {
            int ca = ks * 2 + lb;
            int cb = ks * 2 + bCk;
            uint32_t choA = (uint32_t)((ca ^ swA) << 4);
            uint32_t choB = (uint32_t)((cb ^ swB) << 4);
            uint32_t ah[4][4], al[4][4];
            uint32_t bh0[4], bl0[4], bh1[4], bl1[4];
            #pragma unroll
            for (int mf = 0; mf < 4; mf++) {
                ldsm4(ah[mf], aBase + AHI + mf * 2048u + choA);
                ldsm4(al[mf], aBase + ALO + mf * 2048u + choA);
            }
            ldsm4(bh0, bBase + BHI + choB);
            ldsm4(bl0, bBase + BLO + choB);
            ldsm4(bh1, bBase + BHI + 2048u + choB);
            ldsm4(bl1, bBase + BLO + 2048u + choB);
            #pragma unroll
            for (int mf = 0; mf < 4; mf++) {
                #pragma unroll
                for (int nf = 0; nf < 4; nf++) {
                    const uint32_t* BHf = (nf < 2) ? bh0 : bh1;
                    const uint32_t* BLf = (nf < 2) ? bl0 : bl1;
                    uint32_t bH0 = BHf[(nf & 1) * 2], bH1 = BHf[(nf & 1) * 2 + 1];
                    uint32_t bL0 = BLf[(nf & 1) * 2], bL1 = BLf[(nf & 1) * 2 + 1];
                    float* C = acc[mf][nf];
                    mma_bf(C, ah[mf], bH0, bH1);
                    mma_bf(C, ah[mf], bL0, bL1);
                    mma_bf(C, al[mf], bH0, bH1);
                }
            }
        }
        __syncthreads();
    }

    // epilogue: rs*bias + relu, store fp32 h, fused BN stats
    int colq = 2 * (lane & 3);
    int rowq = lane >> 2;
    float* sstat = (float*)smem;
    sstat[tid] = 0.0f;
    __syncthreads();

    float lsum[8], lsq[8];
    #pragma unroll
    for (int j = 0; j < 8; j++) { lsum[j] = 0.0f; lsq[j] = 0.0f; }
    #pragma unroll
    for (int mf = 0; mf < 4; mf++) {
        size_t r0 = m0 + wm0 + mf * 16 + rowq;
        size_t r1 = r0 + 8;
        float rs0 = g_rs[(int)(r0 % NJ)];
        float rs1 = g_rs[(int)(r1 % NJ)];
        bool v0 = r0 < MROWS, v1 = r1 < MROWS;
        #pragma unroll
        for (int nf = 0; nf < 4; nf++) {
            int c = n0 + wn0 + nf * 8 + colq;
            float b0 = g_bias[c], b1 = g_bias[c + 1];
            float x0 = fmaxf(acc[mf][nf][0] + rs0 * b0, 0.0f);
            float x1 = fmaxf(acc[mf][nf][1] + rs0 * b1, 0.0f);
            float x2 = fmaxf(acc[mf][nf][2] + rs1 * b0, 0.0f);
            float x3 = fmaxf(acc[mf][nf][3] + rs1 * b1, 0.0f);
            *(float2*)(g_h + r0 * DOUT + c) = make_float2(x0, x1);
            *(float2*)(g_h + r1 * DOUT + c) = make_float2(x2, x3);
            if (v0) {
                lsum[nf*2]   += x0; lsq[nf*2]   = fmaf(x0, x0, lsq[nf*2]);
                lsum[nf*2+1] += x1; lsq[nf*2+1] = fmaf(x1, x1, lsq[nf*2+1]);
            }
            if (v1) {
                lsum[nf*2]   += x2; lsq[nf*2]   = fmaf(x2, x2, lsq[nf*2]);
                lsum[nf*2+1] += x3; lsq[nf*2+1] = fmaf(x3, x3, lsq[nf*2+1]);
            }
        }
    }
    #pragma unroll
    for (int o = 4; o < 32; o <<= 1) {
        #pragma unroll
        for (int j = 0; j < 8; j++) {
            lsum[j] += __shfl_xor_sync(0xffffffffu, lsum[j], o);
            lsq[j]  += __shfl_xor_sync(0xffffffffu, lsq[j],  o);
        }
    }
    if (lane < 4) {
        #pragma unroll
        for (int nf = 0; nf < 4; nf++) {
            #pragma unroll
            for (int j = 0; j < 2; j++) {
                int cb = wn0 + nf * 8 + 2 * lane + j;
                atomicAdd(&sstat[cb],       lsum[nf*2 + j]);
                atomicAdd(&sstat[128 + cb], lsq[nf*2 + j]);
            }
        }
    }
    __syncthreads();
    if (tid < 128) atomicAdd(&g_bnsum[n0 + tid], sstat[tid]);
    else           atomicAdd(&g_bnsq [n0 + tid - 128], sstat[tid]);
}

// ---------------- GEMM2/3: HMMA fp16 single-pass ----------------
// Block 128x128, BK=64, 8 warps (2M x 4N), warp tile 64x32. 32 KB smem.
// MODE 1: mid = relu(hn @ mw1^T + b1)  (half out)
// MODE 2: out = mid @ mw2^T + b2       (fp32 out, row-guarded)
template<int K, int MODE>
__global__ void __launch_bounds__(256, 2)
mma_gemm_h(const float* __restrict__ biasx, float* __restrict__ Cout) {
    extern __shared__ char smem[];
    const uint32_t sb = smem_u32(smem);
    constexpr uint32_t BOF = 16384;

    int tid = threadIdx.x;
    int wid = tid >> 5, lane = tid & 31;
    int wm0 = (wid & 1) * 64;
    int wn0 = (wid >> 1) * 32;

    size_t m0 = (size_t)blockIdx.y * 128;
    int    n0 = blockIdx.x * 128;

    const __half* A = (MODE == 1) ? g_hnh  : g_midh;
    const __half* B = (MODE == 1) ? g_mw1h : g_mw2h;

    float acc[4][4][4] = {};

    int la = lane & 15, lb = lane >> 4;
    int swA = la & 7;
    uint32_t aBase = sb + (uint32_t)(wm0 + la) * 128u;
    uint32_t browB = (uint32_t)(wn0 + (lane & 7) + ((lane >> 4) << 3));
    int bCk = (lane >> 3) & 1;
    int swB = lane & 7;
    uint32_t bBase = sb + BOF + browB * 128u;

    int srr = tid >> 3, scc = tid & 7;

    #pragma unroll
    for (int kc = 0; kc < K / 64; kc++) {
        #pragma unroll
        for (int q = 0; q < 4; q++) {
            int r = srr + q * 32;
            size_t goA = (m0 + r) * (size_t)K + kc * 64 + scc * 8;
            size_t goB = (size_t)(n0 + r) * K + kc * 64 + scc * 8;
            uint32_t so = (uint32_t)(r * 128 + ((scc ^ (r & 7)) << 4));
            cpa16(sb + so, A + goA);
            cpa16(sb + BOF + so, B + goB);
        }
        CP_COMMIT();
        CP_WAIT0();
        __syncthreads();

        #pragma unroll
        for (int ks = 0; ks < 4; ks++) {
            int ca = ks * 2 + lb;
            int cb = ks * 2 + bCk;
            uint32_t choA = (uint32_t)((ca ^ swA) << 4);
            uint32_t choB = (uint32_t)((cb ^ swB) << 4);
            uint32_t ah[4][4];
            uint32_t bh0[4], bh1[4];
            #pragma unroll
            for (int mf = 0; mf < 4; mf++)
                ldsm4(ah[mf], aBase + mf * 2048u + choA);
            ldsm4(bh0, bBase + choB);
            ldsm4(bh1, bBase + 2048u + choB);
            #pragma unroll
            for (int mf = 0; mf < 4; mf++) {
                #pragma unroll
                for (int nf = 0; nf < 4; nf++) {
                    const uint32_t* BHf = (nf < 2) ? bh0 : bh1;
                    uint32_t b0 = BHf[(nf & 1) * 2], b1 = BHf[(nf & 1) * 2 + 1];
                    mma_fp(acc[mf][nf], ah[mf], b0, b1);
                }
            }
        }
        __syncthreads();
    }

    // epilogue
    int colq = 2 * (lane & 3);
    int rowq = lane >> 2;
    if (MODE == 1) {
        #pragma unroll
        for (int mf = 0; mf < 4; mf++) {
            size_t r0 = m0 + wm0 + mf * 16 + rowq;
            size_t r1 = r0 + 8;
            #pragma unroll
            for (int nf = 0; nf < 4; nf++) {
                int c = n0 + wn0 + nf * 8 + colq;
                float b0 = biasx[c], b1 = biasx[c + 1];
                float x0 = fmaxf(acc[mf][nf][0] + b0, 0.0f);
                float x1 = fmaxf(acc[mf][nf][1] + b1, 0.0f);
                float x2 = fmaxf(acc[mf][nf][2] + b0, 0.0f);
                float x3 = fmaxf(acc[mf][nf][3] + b1, 0.0f);
                *(uint32_t*)(g_midh + r0 * DMID + c) = pack_half2(x0, x1);
                *(uint32_t*)(g_midh + r1 * DMID + c) = pack_half2(x2, x3);
            }
        }
    } else {
        #pragma unroll
        for (int mf = 0; mf < 4; mf++) {
            size_t r0 = m0 + wm0 + mf * 16 + rowq;
            size_t r1 = r0 + 8;
            #pragma unroll
            for (int nf = 0; nf < 4; nf++) {
                int c = n0 + wn0 + nf * 8 + colq;
                float b0 = biasx[c], b1 = biasx[c + 1];
                if (r0 < MROWS)
                    *(float2*)(Cout + r0 * DOUT + c) =
                        make_float2(acc[mf][nf][0] + b0, acc[mf][nf][1] + b1);
                if (r1 < MROWS)
                    *(float2*)(Cout + r1 * DOUT + c) =
                        make_float2(acc[mf][nf][2] + b0, acc[mf][nf][3] + b1);
            }
        }
    }
}

// ---------------- BN finalize ----------------
__global__ void bnfin_kernel(const float* __restrict__ bng, const float* __restrict__ bnb) {
    int c = threadIdx.x;
    const float inv = 1.0f / (float)MROWS;
    float mean = g_bnsum[c] * inv;
    float var  = g_bnsq[c] * inv - mean * mean;
    float sc   = bng[c] * rsqrtf(var + EPSV);
    g_scale[c] = sc;
    g_shift[c] = bnb[c] - mean * sc;
}

// ---------------- fused BN + LayerNorm -> fp16 hn ----------------
__global__ void bnln_kernel(const float* __restrict__ lng, const float* __restrict__ lnb) {
    int warp = threadIdx.x >> 5, lane = threadIdx.x & 31;
    size_t row = (size_t)blockIdx.x * 8 + warp;
    const float* hr = g_h + row * DOUT;
    float v[8];
    float s = 0.0f, sq = 0.0f;
    #pragma unroll
    for (int e = 0; e < 8; e++) {
        int c = lane + 32 * e;
        float t = fmaf(hr[c], g_scale[c], g_shift[c]);
        v[e] = t; s += t; sq = fmaf(t, t, sq);
    }
    #pragma unroll
    for (int o = 16; o > 0; o >>= 1) {
        s  += __shfl_xor_sync(0xffffffffu, s,  o);
        sq += __shfl_xor_sync(0xffffffffu, sq, o);
    }
    float mu  = s * (1.0f / DOUT);
    float var = sq * (1.0f / DOUT) - mu * mu;
    float inv = rsqrtf(var + EPSV);
    #pragma unroll
    for (int e = 0; e < 8; e++) {
        int c = lane + 32 * e;
        float o = fmaf((v[e] - mu) * inv, lng[c], lnb[c]);
        g_hnh[row * DOUT + c] = __float2half_rn(o);
    }
}

// ---------------------------------------------------------------------------
extern "C" void kernel_launch(void* const* d_in, const int* in_sizes, int n_in,
                              void* d_out, int out_size) {
    const float* x   = (const float*)d_in[0];
    const float* adj = (const float*)d_in[1];
    const float* w1  = (const float*)d_in[2];
    const float* b1  = (const float*)d_in[3];
    const float* w2  = (const float*)d_in[4];
    const float* b2  = (const float*)d_in[5];
    const float* bng = (const float*)d_in[6];
    const float* bnb = (const float*)d_in[7];
    const float* lng = (const float*)d_in[8];
    const float* lnb = (const float*)d_in[9];
    const float* mw1 = (const float*)d_in[10];
    const float* mb1 = (const float*)d_in[11];
    const float* mw2 = (const float*)d_in[12];
    const float* mb2 = (const float*)d_in[13];
    float* out = (float*)d_out;

    const int SMEM1 = 65536;   // GEMM1: 64 KB dynamic (opt-in)
    const int SMEMH = 32768;   // fp16 GEMMs: 32 KB (within default limit)

    // host-side config, not an allocation; idempotent, capture-safe
    cudaFuncSetAttribute(mma_gemm1, cudaFuncAttributeMaxDynamicSharedMemorySize, SMEM1);

    prep_kernel<<<1280, 256>>>(w1, b1, w2, b2, adj, mw1, mw2);
    padzero_kernel<<<192, 256>>>();
    agg_kernel<<<NSAMP, 256>>>(x, adj);
    // GEMM1 (split-bf16): h = relu(xa @ (w1+w2)^T + rs*bias), fused BN stats
    mma_gemm1<<<dim3(2, MTILES), 256, SMEM1>>>();
    bnfin_kernel<<<1, DOUT>>>(bng, bnb);
    bnln_kernel<<<MROWS / 8, 256>>>(lng, lnb);
    // GEMM2 (fp16): mid = relu(hn @ mlp_w1^T + mlp_b1)
    mma_gemm_h<256, 1><<<dim3(4, MTILES), 256, SMEMH>>>(mb1, nullptr);
    // GEMM3 (fp16): out = mid @ mlp_w2^T + mlp_b2
    mma_gemm_h<512, 2><<<dim3(2, MTILES), 256, SMEMH>>>(mb2, out);
}

// round 10
// speedup vs baseline: 2.2621x; 1.1895x over previous
#include <cuda_runtime.h>
#include <cuda_bf16.h>
#include <cuda_fp16.h>
#include <cstdint>

// ---------------- problem constants ----------------
#define NSAMP  15552
#define NJ     17
#define MROWS  (NSAMP*NJ)        // 264384
#define MTILES 2066              // ceil(MROWS/128)
#define MPAD   (MTILES*128)      // 264448
#define DIN    256
#define DOUT   256
#define DMID   512
#define EPSV   1e-5f

// ---------------- scratch (device globals; no runtime alloc) ----------------
static __device__ __half g_xah  [(size_t)MPAD * DIN];
static __device__ float  g_h    [(size_t)MPAD * DOUT];
static __device__ __half g_hnh  [(size_t)MPAD * DOUT];
static __device__ __half g_midh [(size_t)MPAD * DMID];

static __device__ __half g_wh   [DOUT * DIN];
static __device__ __half g_mw1h [DMID * DOUT];
static __device__ __half g_mw2h [DOUT * DMID];

static __device__ float g_bias [DOUT];
static __device__ float g_rs   [NJ];
static __device__ float g_bnsum[DOUT];
static __device__ float g_bnsq [DOUT];
static __device__ float g_scale[DOUT];
static __device__ float g_shift[DOUT];

// ---------------- helpers ----------------
__device__ __forceinline__ uint32_t smem_u32(const void* p) {
    uint32_t a;
    asm("{ .reg .u64 t; cvta.to.shared.u64 t, %1; cvt.u32.u64 %0, t; }" : "=r"(a) : "l"(p));
    return a;
}
__device__ __forceinline__ void ldsm4(uint32_t* r, uint32_t addr) {
    asm volatile("ldmatrix.sync.aligned.m8n8.x4.shared.b16 {%0,%1,%2,%3}, [%4];"
                 : "=r"(r[0]), "=r"(r[1]), "=r"(r[2]), "=r"(r[3]) : "r"(addr));
}
__device__ __forceinline__ void mma_fp(float* c, const uint32_t* a, uint32_t b0, uint32_t b1) {
    asm volatile("mma.sync.aligned.m16n8k16.row.col.f32.f16.f16.f32 "
                 "{%0,%1,%2,%3}, {%4,%5,%6,%7}, {%8,%9}, {%0,%1,%2,%3};"
                 : "+f"(c[0]), "+f"(c[1]), "+f"(c[2]), "+f"(c[3])
                 : "r"(a[0]), "r"(a[1]), "r"(a[2]), "r"(a[3]), "r"(b0), "r"(b1));
}
// L1-bypass async copy (L2 -> smem), 16B
__device__ __forceinline__ void cpa16(uint32_t dst, const void* src) {
    asm volatile("cp.async.cg.shared.global [%0], [%1], 16;" :: "r"(dst), "l"(src));
}
#define CP_COMMIT() asm volatile("cp.async.commit_group;" ::: "memory")
#define CP_WAIT0()  asm volatile("cp.async.wait_group 0;" ::: "memory")

__device__ __forceinline__ uint32_t pack_half2(float a, float b) {
    __half2 h = __floats2half2_rn(a, b);
    return *(uint32_t*)&h;
}

// ---------------- K0: prep ----------------
__global__ void prep_kernel(const float* __restrict__ w1, const float* __restrict__ b1,
                            const float* __restrict__ w2, const float* __restrict__ b2,
                            const float* __restrict__ adj,
                            const float* __restrict__ mw1, const float* __restrict__ mw2) {
    int bid = blockIdx.x, tid = threadIdx.x;
    if (bid < 256) {
        int i = bid * 256 + tid;
        g_wh[i] = __float2half_rn(w1[i] + w2[i]);
    } else if (bid < 768) {
        int i = (bid - 256) * 256 + tid;
        g_mw1h[i] = __float2half_rn(mw1[i]);
    } else {
        int i = (bid - 768) * 256 + tid;
        g_mw2h[i] = __float2half_rn(mw2[i]);
    }
    if (bid == 0) {
        g_bias[tid]  = b1[tid] + b2[tid];
        g_bnsum[tid] = 0.0f;
        g_bnsq[tid]  = 0.0f;
        if (tid < NJ) {
            float s = 0.0f;
            #pragma unroll
            for (int j = 0; j < NJ; j++) s += adj[tid * NJ + j];
            g_rs[tid] = s;
        }
    }
}

// zero the padded tail rows of xa / hn (half)
__global__ void padzero_kernel() {
    int idx = blockIdx.x * 256 + threadIdx.x;       // [0, 32768)
    int region = idx >> 14, off = idx & 16383;
    size_t p = (size_t)MROWS * 256 + off;
    if (region == 0) g_xah[p] = __float2half(0.0f);
    else             g_hnh[p] = __float2half(0.0f);
}

// ---------------- K1: adjacency aggregation -> fp16 ----------------
__global__ void agg_kernel(const float* __restrict__ x, const float* __restrict__ adj) {
    __shared__ float sadj[NJ * NJ];
    int t = threadIdx.x;
    for (int i = t; i < NJ * NJ; i += 256) sadj[i] = adj[i];
    __syncthreads();
    size_t base = (size_t)blockIdx.x * NJ * DIN + t;
    const float* xs = x + base;
    float xv[NJ];
    #pragma unroll
    for (int j = 0; j < NJ; j++) xv[j] = xs[(size_t)j * DIN];
    #pragma unroll
    for (int i = 0; i < NJ; i++) {
        float a = 0.0f;
        #pragma unroll
        for (int j = 0; j < NJ; j++) a = fmaf(sadj[i * NJ + j], xv[j], a);
        g_xah[base + (size_t)i * DIN] = __float2half_rn(a);
    }
}

// ---------------- unified fp16 HMMA GEMM ----------------
// Block 128x128, BK=64, 8 warps (2M x 4N), warp tile 64x32. 32 KB smem.
// MODE 0: h = relu(xa @ w^T + rs*bias)   (fp32 out + fused BN stats)
// MODE 1: mid = relu(hn @ mw1^T + b1)    (half out)
// MODE 2: out = mid @ mw2^T + b2         (fp32 out, row-guarded)
template<int K, int MODE>
__global__ void __launch_bounds__(256, 2)
mma_gemm_h(const float* __restrict__ biasx, float* __restrict__ Cout) {
    extern __shared__ char smem[];
    const uint32_t sb = smem_u32(smem);
    constexpr uint32_t BOF = 16384;

    int tid = threadIdx.x;
    int wid = tid >> 5, lane = tid & 31;
    int wm0 = (wid & 1) * 64;
    int wn0 = (wid >> 1) * 32;

    size_t m0 = (size_t)blockIdx.y * 128;
    int    n0 = blockIdx.x * 128;

    const __half* A = (MODE == 0) ? g_xah : ((MODE == 1) ? g_hnh  : g_midh);
    const __half* B = (MODE == 0) ? g_wh  : ((MODE == 1) ? g_mw1h : g_mw2h);

    float acc[4][4][4] = {};

    int la = lane & 15, lb = lane >> 4;
    int swA = la & 7;
    uint32_t aBase = sb + (uint32_t)(wm0 + la) * 128u;
    uint32_t browB = (uint32_t)(wn0 + (lane & 7) + ((lane >> 4) << 3));
    int bCk = (lane >> 3) & 1;
    int swB = lane & 7;
    uint32_t bBase = sb + BOF + browB * 128u;

    int srr = tid >> 3, scc = tid & 7;

    #pragma unroll
    for (int kc = 0; kc < K / 64; kc++) {
        #pragma unroll
        for (int q = 0; q < 4; q++) {
            int r = srr + q * 32;
            size_t goA = (m0 + r) * (size_t)K + kc * 64 + scc * 8;
            size_t goB = (size_t)(n0 + r) * K + kc * 64 + scc * 8;
            uint32_t so = (uint32_t)(r * 128 + ((scc ^ (r & 7)) << 4));
            cpa16(sb + so, A + goA);
            cpa16(sb + BOF + so, B + goB);
        }
        CP_COMMIT();
        CP_WAIT0();
        __syncthreads();

        #pragma unroll
        for (int ks = 0; ks < 4; ks++) {
            int ca = ks * 2 + lb;
            int cb = ks * 2 + bCk;
            uint32_t choA = (uint32_t)((ca ^ swA) << 4);
            uint32_t choB = (uint32_t)((cb ^ swB) << 4);
            uint32_t ah[4][4];
            uint32_t bh0[4], bh1[4];
            #pragma unroll
            for (int mf = 0; mf < 4; mf++)
                ldsm4(ah[mf], aBase + mf * 2048u + choA);
            ldsm4(bh0, bBase + choB);
            ldsm4(bh1, bBase + 2048u + choB);
            #pragma unroll
            for (int mf = 0; mf < 4; mf++) {
                #pragma unroll
                for (int nf = 0; nf < 4; nf++) {
                    const uint32_t* BHf = (nf < 2) ? bh0 : bh1;
                    uint32_t b0 = BHf[(nf & 1) * 2], b1 = BHf[(nf & 1) * 2 + 1];
                    mma_fp(acc[mf][nf], ah[mf], b0, b1);
                }
            }
        }
        __syncthreads();
    }

    // ---------------- epilogue ----------------
    int colq = 2 * (lane & 3);
    int rowq = lane >> 2;

    if (MODE == 0) {
        // rs*bias + relu, fp32 store, fused BN stats (scratch aliases smem)
        float* sstat = (float*)smem;
        sstat[tid] = 0.0f;
        __syncthreads();

        float lsum[8], lsq[8];
        #pragma unroll
        for (int j = 0; j < 8; j++) { lsum[j] = 0.0f; lsq[j] = 0.0f; }
        #pragma unroll
        for (int mf = 0; mf < 4; mf++) {
            size_t r0 = m0 + wm0 + mf * 16 + rowq;
            size_t r1 = r0 + 8;
            float rs0 = g_rs[(int)(r0 % NJ)];
            float rs1 = g_rs[(int)(r1 % NJ)];
            bool v0 = r0 < MROWS, v1 = r1 < MROWS;
            #pragma unroll
            for (int nf = 0; nf < 4; nf++) {
                int c = n0 + wn0 + nf * 8 + colq;
                float b0 = g_bias[c], b1 = g_bias[c + 1];
                float x0 = fmaxf(acc[mf][nf][0] + rs0 * b0, 0.0f);
                float x1 = fmaxf(acc[mf][nf][1] + rs0 * b1, 0.0f);
                float x2 = fmaxf(acc[mf][nf][2] + rs1 * b0, 0.0f);
                float x3 = fmaxf(acc[mf][nf][3] + rs1 * b1, 0.0f);
                *(float2*)(g_h + r0 * DOUT + c) = make_float2(x0, x1);
                *(float2*)(g_h + r1 * DOUT + c) = make_float2(x2, x3);
                if (v0) {
                    lsum[nf*2]   += x0; lsq[nf*2]   = fmaf(x0, x0, lsq[nf*2]);
                    lsum[nf*2+1] += x1; lsq[nf*2+1] = fmaf(x1, x1, lsq[nf*2+1]);
                }
                if (v1) {
                    lsum[nf*2]   += x2; lsq[nf*2]   = fmaf(x2, x2, lsq[nf*2]);
                    lsum[nf*2+1] += x3; lsq[nf*2+1] = fmaf(x3, x3, lsq[nf*2+1]);
                }
            }
        }
        #pragma unroll
        for (int o = 4; o < 32; o <<= 1) {
            #pragma unroll
            for (int j = 0; j < 8; j++) {
                lsum[j] += __shfl_xor_sync(0xffffffffu, lsum[j], o);
                lsq[j]  += __shfl_xor_sync(0xffffffffu, lsq[j],  o);
            }
        }
        if (lane < 4) {
            #pragma unroll
            for (int nf = 0; nf < 4; nf++) {
                #pragma unroll
                for (int j = 0; j < 2; j++) {
                    int cb = wn0 + nf * 8 + 2 * lane + j;
                    atomicAdd(&sstat[cb],       lsum[nf*2 + j]);
                    atomicAdd(&sstat[128 + cb], lsq[nf*2 + j]);
                }
            }
        }
        __syncthreads();
        if (tid < 128) atomicAdd(&g_bnsum[n0 + tid], sstat[tid]);
        else           atomicAdd(&g_bnsq [n0 + tid - 128], sstat[tid]);
    } else if (MODE == 1) {
        #pragma unroll
        for (int mf = 0; mf < 4; mf++) {
            size_t r0 = m0 + wm0 + mf * 16 + rowq;
            size_t r1 = r0 + 8;
            #pragma unroll
            for (int nf = 0; nf < 4; nf++) {
                int c = n0 + wn0 + nf * 8 + colq;
                float b0 = biasx[c], b1 = biasx[c + 1];
                float x0 = fmaxf(acc[mf][nf][0] + b0, 0.0f);
                float x1 = fmaxf(acc[mf][nf][1] + b1, 0.0f);
                float x2 = fmaxf(acc[mf][nf][2] + b0, 0.0f);
                float x3 = fmaxf(acc[mf][nf][3] + b1, 0.0f);
                *(uint32_t*)(g_midh + r0 * DMID + c) = pack_half2(x0, x1);
                *(uint32_t*)(g_midh + r1 * DMID + c) = pack_half2(x2, x3);
            }
        }
    } else {
        #pragma unroll
        for (int mf = 0; mf < 4; mf++) {
            size_t r0 = m0 + wm0 + mf * 16 + rowq;
            size_t r1 = r0 + 8;
            #pragma unroll
            for (int nf = 0; nf < 4; nf++) {
                int c = n0 + wn0 + nf * 8 + colq;
                float b0 = biasx[c], b1 = biasx[c + 1];
                if (r0 < MROWS)
                    *(float2*)(Cout + r0 * DOUT + c) =
                        make_float2(acc[mf][nf][0] + b0, acc[mf][nf][1] + b1);
                if (r1 < MROWS)
                    *(float2*)(Cout + r1 * DOUT + c) =
                        make_float2(acc[mf][nf][2] + b0, acc[mf][nf][3] + b1);
            }
        }
    }
}

// ---------------- BN finalize ----------------
__global__ void bnfin_kernel(const float* __restrict__ bng, const float* __restrict__ bnb) {
    int c = threadIdx.x;
    const float inv = 1.0f / (float)MROWS;
    float mean = g_bnsum[c] * inv;
    float var  = g_bnsq[c] * inv - mean * mean;
    float sc   = bng[c] * rsqrtf(var + EPSV);
    g_scale[c] = sc;
    g_shift[c] = bnb[c] - mean * sc;
}

// ---------------- fused BN + LayerNorm -> fp16 hn ----------------
__global__ void bnln_kernel(const float* __restrict__ lng, const float* __restrict__ lnb) {
    int warp = threadIdx.x >> 5, lane = threadIdx.x & 31;
    size_t row = (size_t)blockIdx.x * 8 + warp;
    const float* hr = g_h + row * DOUT;
    float v[8];
    float s = 0.0f, sq = 0.0f;
    #pragma unroll
    for (int e = 0; e < 8; e++) {
        int c = lane + 32 * e;
        float t = fmaf(hr[c], g_scale[c], g_shift[c]);
        v[e] = t; s += t; sq = fmaf(t, t, sq);
    }
    #pragma unroll
    for (int o = 16; o > 0; o >>= 1) {
        s  += __shfl_xor_sync(0xffffffffu, s,  o);
        sq += __shfl_xor_sync(0xffffffffu, sq, o);
    }
    float mu  = s * (1.0f / DOUT);
    float var = sq * (1.0f / DOUT) - mu * mu;
    float inv = rsqrtf(var + EPSV);
    #pragma unroll
    for (int e = 0; e < 8; e++) {
        int c = lane + 32 * e;
        float o = fmaf((v[e] - mu) * inv, lng[c], lnb[c]);
        g_hnh[row * DOUT + c] = __float2half_rn(o);
    }
}

// ---------------------------------------------------------------------------
extern "C" void kernel_launch(void* const* d_in, const int* in_sizes, int n_in,
                              void* d_out, int out_size) {
    const float* x   = (const float*)d_in[0];
    const float* adj = (const float*)d_in[1];
    const float* w1  = (const float*)d_in[2];
    const float* b1  = (const float*)d_in[3];
    const float* w2  = (const float*)d_in[4];
    const float* b2  = (const float*)d_in[5];
    const float* bng = (const float*)d_in[6];
    const float* bnb = (const float*)d_in[7];
    const float* lng = (const float*)d_in[8];
    const float* lnb = (const float*)d_in[9];
    const float* mw1 = (const float*)d_in[10];
    const float* mb1 = (const float*)d_in[11];
    const float* mw2 = (const float*)d_in[12];
    const float* mb2 = (const float*)d_in[13];
    float* out = (float*)d_out;

    const int SMEMH = 32768;   // 32 KB dynamic (within default limit)

    prep_kernel<<<1280, 256>>>(w1, b1, w2, b2, adj, mw1, mw2);
    padzero_kernel<<<128, 256>>>();
    agg_kernel<<<NSAMP, 256>>>(x, adj);
    // GEMM1 (fp16): h = relu(xa @ (w1+w2)^T + rs*bias), fused BN stats
    mma_gemm_h<256, 0><<<dim3(2, MTILES), 256, SMEMH>>>(nullptr, nullptr);
    bnfin_kernel<<<1, DOUT>>>(bng, bnb);
    bnln_kernel<<<MROWS / 8, 256>>>(lng, lnb);
    // GEMM2 (fp16): mid = relu(hn @ mlp_w1^T + mlp_b1)
    mma_gemm_h<256, 1><<<dim3(4, MTILES), 256, SMEMH>>>(mb1, nullptr);
    // GEMM3 (fp16): out = mid @ mlp_w2^T + mlp_b2
    mma_gemm_h<512, 2><<<dim3(2, MTILES), 256, SMEMH>>>(mb2, out);
}